// round 9
// baseline (speedup 1.0000x reference)
#include <cuda_runtime.h>
#include <cuda_fp16.h>
#include <math.h>

#define E_DIM 1024
#define H_DIM 2048
#define G3 6144            // 3*H
#define VOCAB 256
#define NBLK 148
#define NTHR 896           // 28 warps: 14 primary + 14 secondary
#define UPB 14

// SMEM: weights [42][2048] fp16 | hs[2048] fp32 | partials[42] fp32
#define WS_BYTES (42 * H_DIM * 2)          // 172032
#define HS_OFF   WS_BYTES
#define PART_OFF (HS_OFF + H_DIM * 4)      // 180224
#define SMEM_TOTAL (PART_OFF + 48 * 4)     // 180416

// ---------------- scratch (static device memory, no allocs) ----------------
__device__ float g_tbl[VOCAB * G3];   // W_ih@emb[v] + b_ih (+b_hh folded for r,z)
__device__ float g_h[2][H_DIM];       // hidden state, double-buffered
__device__ unsigned g_cnt;            // monotonic phased barrier counter

// ---------------- sync primitives --------------------------------------------
__device__ __forceinline__ unsigned ld_acq_gpu(const unsigned* p) {
    unsigned v;
    asm volatile("ld.acquire.gpu.global.b32 %0, [%1];" : "=r"(v) : "l"(p) : "memory");
    return v;
}
__device__ __forceinline__ void red_rel_add1(unsigned* p) {
    asm volatile("red.release.gpu.global.add.u32 [%0], %1;" :: "l"(p), "r"(1u) : "memory");
}

// ---------------- packed f32x2 helpers ---------------------------------------
__device__ __forceinline__ unsigned long long pk(float x, float y) {
    unsigned long long r;
    asm("mov.b64 %0, {%1, %2};" : "=l"(r) : "f"(x), "f"(y));
    return r;
}
__device__ __forceinline__ float2 unpk(unsigned long long v) {
    float2 r;
    asm("mov.b64 {%0, %1}, %2;" : "=f"(r.x), "=f"(r.y) : "l"(v));
    return r;
}
__device__ __forceinline__ void fma2(unsigned long long& d,
                                     unsigned long long a, unsigned long long b) {
    asm("fma.rn.f32x2 %0, %1, %2, %0;" : "+l"(d) : "l"(a), "l"(b));
}
__device__ __forceinline__ void dotq(uint4 w,
    unsigned long long hp0, unsigned long long hp1,
    unsigned long long hp2, unsigned long long hp3,
    unsigned long long& aA, unsigned long long& aB) {
    float2 f0 = __half22float2(*(__half2*)&w.x);
    float2 f1 = __half22float2(*(__half2*)&w.y);
    float2 f2 = __half22float2(*(__half2*)&w.z);
    float2 f3 = __half22float2(*(__half2*)&w.w);
    fma2(aA, pk(f0.x, f0.y), hp0);
    fma2(aB, pk(f1.x, f1.y), hp1);
    fma2(aA, pk(f2.x, f2.y), hp2);
    fma2(aB, pk(f3.x, f3.y), hp3);
}

// ---------------- kernel 1: ih table GEMM + state/counter init --------------
__global__ __launch_bounds__(256) void tbl_kernel(
    const float* __restrict__ emb,
    const float* __restrict__ w_ih,
    const float* __restrict__ b_ih,
    const float* __restrict__ b_hh)
{
    __shared__ float Es[32][33];
    __shared__ float Ws[64][33];
    const int tid = threadIdx.x;
    const int j0 = blockIdx.x * 64;
    const int v0 = blockIdx.y * 32;

    if (blockIdx.x == 0 && blockIdx.y == 0) {
        for (int i = tid; i < 2 * H_DIM; i += 256) ((float*)g_h)[i] = 0.f;
        if (tid == 0) g_cnt = 0u;
    }

    float acc[8] = {0.f, 0.f, 0.f, 0.f, 0.f, 0.f, 0.f, 0.f};
    const int jj = tid & 63;
    const int vb = (tid >> 6) * 8;

    for (int k0 = 0; k0 < E_DIM; k0 += 32) {
        __syncthreads();
        #pragma unroll
        for (int p = 0; p < 4; p++) {
            int idx = tid + p * 256;
            Es[idx >> 5][idx & 31] = emb[(size_t)(v0 + (idx >> 5)) * E_DIM + k0 + (idx & 31)];
        }
        #pragma unroll
        for (int p = 0; p < 8; p++) {
            int idx = tid + p * 256;
            Ws[idx >> 5][idx & 31] = w_ih[(size_t)(j0 + (idx >> 5)) * E_DIM + k0 + (idx & 31)];
        }
        __syncthreads();
        #pragma unroll
        for (int kk = 0; kk < 32; kk++) {
            float w = Ws[jj][kk];
            #pragma unroll
            for (int r = 0; r < 8; r++) acc[r] += w * Es[vb + r][kk];
        }
    }
    const int j = j0 + jj;
    float bias = b_ih[j] + ((j < 2 * H_DIM) ? b_hh[j] : 0.f);
    #pragma unroll
    for (int r = 0; r < 8; r++)
        g_tbl[(size_t)(v0 + vb + r) * G3 + j] = acc[r] + bias;
}

// ---------------- kernel 2: persistent GRU, warp-pair per unit ---------------
// Unit u = b*14 + w: primary warp w handles k in [0,1024), secondary warp
// w+14 handles k in [1024,2048). Secondary deposits 3 partials in SMEM;
// primary lane 0 combines and finishes the GRU cell. All weights SMEM fp16.
// Grid sync = single monotonic counter, one release-RED per block per step.
__global__ void __launch_bounds__(NTHR, 1) gru_kernel(
    const int*   __restrict__ x,
    const int*   __restrict__ lenp,
    const float* __restrict__ w_hh,    // [G3, H] fp32
    const float* __restrict__ b_hh,    // [G3]
    const float* __restrict__ dec_emb, // [128, E]
    float*       __restrict__ out,     // [E + H]
    int n_x)
{
    extern __shared__ __align__(16) unsigned char smem_raw[];
    __half* ws   = (__half*)smem_raw;
    float*  hs   = (float*)(smem_raw + HS_OFF);
    float*  part = (float*)(smem_raw + PART_OFF);

    const int tid  = threadIdx.x;
    const int b    = blockIdx.x;
    const int lane = tid & 31;
    const int wid  = tid >> 5;

    const int u0 = b * UPB;
    int nu = H_DIM - u0;
    if (nu > UPB) nu = UPB;
    if (nu < 0) nu = 0;

    const bool secondary = (wid >= 14);
    const int uloc = secondary ? (wid - 14) : wid;
    const bool active = (uloc < nu);
    const int u = u0 + uloc;
    const int cbase = secondary ? 4 : 0;   // which half of k this warp covers

    int steps = lenp[0] + 1;
    if (steps > n_x) steps = n_x;

    // ---- prologue: convert block's 3*nu weight rows fp32 -> fp16 SMEM ----
    // local row lr = 3*uloc + r  <->  global row r*H + u0 + uloc
    {
        const int tot = 3 * nu * 512;   // float4s
        for (int idx = tid; idx < tot; idx += NTHR) {
            const int lr = idx >> 9;
            const int pos = idx & 511;
            const int ul = lr / 3, r = lr - 3 * ul;
            const int row = r * H_DIM + u0 + ul;
            float4 v = __ldcs(((const float4*)w_hh) + (size_t)row * 512 + pos);
            uint2 o; __half2 h;
            h = __floats2half2_rn(v.x, v.y); o.x = *(unsigned*)&h;
            h = __floats2half2_rn(v.z, v.w); o.y = *(unsigned*)&h;
            ((uint2*)(ws + (size_t)lr * H_DIM))[pos] = o;
        }
    }
    __syncthreads();

    const uint4* wr0 = (const uint4*)(ws + (size_t)(3 * uloc)     * H_DIM);
    const uint4* wr1 = (const uint4*)(ws + (size_t)(3 * uloc + 1) * H_DIM);
    const uint4* wr2 = (const uint4*)(ws + (size_t)(3 * uloc + 2) * H_DIM);
    const float4* hs4 = (const float4*)hs;

    float bhn = 0.f;
    if (!secondary && active && lane == 0) bhn = __ldg(&b_hh[2 * H_DIM + u]);
    float hold = 0.f;   // primary lane0: h(t) for this unit, register-resident

    unsigned target = 0;

    for (int t = 0; t < steps; ++t) {
        // hoisted step-t constants (L2 latency hides under detect)
        float ih_r = 0.f, ih_z = 0.f, ih_n = 0.f;
        if (!secondary && active && lane == 0) {
            const int xt = __ldg(&x[t]);
            const float* __restrict__ tbl = g_tbl + (size_t)xt * G3;
            ih_r = __ldg(&tbl[u]);
            ih_z = __ldg(&tbl[u + H_DIM]);
            ih_n = __ldg(&tbl[u + 2 * H_DIM]);
        }

        // ---- detect: all blocks finished step t-1 ----
        if (tid == 0) {
            while (ld_acq_gpu(&g_cnt) < target) { }
        }
        __syncthreads();                                   // A

        // ---- stage h(t) into SMEM ----
        if (tid < 512) {
            float4 v = __ldcg(((const float4*)g_h[t & 1]) + tid);
            ((float4*)hs)[tid] = v;
        }
        __syncthreads();                                   // B

        float a0 = 0.f, a1 = 0.f, a2 = 0.f;
        if (active) {
            unsigned long long a00 = 0ull, a01 = 0ull;
            unsigned long long a10 = 0ull, a11 = 0ull;
            unsigned long long a20 = 0ull, a21 = 0ull;
            #pragma unroll
            for (int c = 0; c < 4; c++) {
                const int cg = cbase + c;
                float4 h0 = hs4[cg * 64 + lane * 2];
                float4 h1 = hs4[cg * 64 + lane * 2 + 1];
                unsigned long long hp0 = pk(h0.x, h0.y);
                unsigned long long hp1 = pk(h0.z, h0.w);
                unsigned long long hp2 = pk(h1.x, h1.y);
                unsigned long long hp3 = pk(h1.z, h1.w);
                uint4 q0 = wr0[cg * 32 + lane];
                uint4 q1 = wr1[cg * 32 + lane];
                uint4 q2 = wr2[cg * 32 + lane];
                dotq(q0, hp0, hp1, hp2, hp3, a00, a01);
                dotq(q1, hp0, hp1, hp2, hp3, a10, a11);
                dotq(q2, hp0, hp1, hp2, hp3, a20, a21);
            }
            float2 s;
            s = unpk(a00); a0 = s.x + s.y;  s = unpk(a01); a0 += s.x + s.y;
            s = unpk(a10); a1 = s.x + s.y;  s = unpk(a11); a1 += s.x + s.y;
            s = unpk(a20); a2 = s.x + s.y;  s = unpk(a21); a2 += s.x + s.y;
            #pragma unroll
            for (int o = 16; o; o >>= 1) {
                a0 += __shfl_xor_sync(0xffffffffu, a0, o);
                a1 += __shfl_xor_sync(0xffffffffu, a1, o);
                a2 += __shfl_xor_sync(0xffffffffu, a2, o);
            }
            if (secondary && lane == 0) {
                part[uloc * 3 + 0] = a0;
                part[uloc * 3 + 1] = a1;
                part[uloc * 3 + 2] = a2;
            }
        }
        __syncthreads();                                   // C (partials + hs reads done)

        if (!secondary && active && lane == 0) {
            a0 += part[uloc * 3 + 0];
            a1 += part[uloc * 3 + 1];
            a2 += part[uloc * 3 + 2];
            float r = 1.f / (1.f + __expf(-(a0 + ih_r)));  // biases folded in tbl
            float z = 1.f / (1.f + __expf(-(a1 + ih_z)));
            float v = ih_n + r * (a2 + bhn);
            float e = __expf(2.f * v);
            float n = 1.f - __fdividef(2.f, e + 1.f);       // tanh(v)
            float hnew = (1.f - z) * n + z * hold;
            hold = hnew;
            __stcg(&g_h[(t & 1) ^ 1][u], hnew);
        }
        __syncthreads();                                   // D (all h stores done)

        if (tid == 0) red_rel_add1(&g_cnt);
        target += NBLK;
    }

    if (b == 0) {
        if (tid == 0) {
            while (ld_acq_gpu(&g_cnt) < target) { }
        }
        __syncthreads();
        const int last = steps & 1;
        for (int i = tid; i < E_DIM; i += NTHR) out[i] = dec_emb[2 * E_DIM + i];
        for (int i = tid; i < H_DIM; i += NTHR) out[E_DIM + i] = __ldcg(&g_h[last][i]);
    }
}

// ---------------- launch ----------------------------------------------------
extern "C" void kernel_launch(void* const* d_in, const int* in_sizes, int n_in,
                              void* d_out, int out_size) {
    const int*   x       = (const int*)d_in[0];
    const int*   lenp    = (const int*)d_in[1];
    const float* enc_emb = (const float*)d_in[2];
    const float* w_ih    = (const float*)d_in[3];
    const float* w_hh    = (const float*)d_in[4];
    const float* b_ih    = (const float*)d_in[5];
    const float* b_hh    = (const float*)d_in[6];
    const float* dec_emb = (const float*)d_in[7];
    float* out = (float*)d_out;
    const int n_x = in_sizes[0];

    static int attr_set = 0;
    if (!attr_set) {
        cudaFuncSetAttribute(gru_kernel, cudaFuncAttributeMaxDynamicSharedMemorySize,
                             SMEM_TOTAL);
        attr_set = 1;
    }

    dim3 tgrid(G3 / 64, VOCAB / 32);   // 96 x 8
    tbl_kernel<<<tgrid, 256>>>(enc_emb, w_ih, b_ih, b_hh);
    gru_kernel<<<NBLK, NTHR, SMEM_TOTAL>>>(x, lenp, w_hh, b_hh, dec_emb, out, n_x);
}

// round 10
// speedup vs baseline: 1.3621x; 1.3621x over previous
#include <cuda_runtime.h>
#include <cuda_fp16.h>
#include <math.h>

#define E_DIM 1024
#define H_DIM 2048
#define G3 6144            // 3*H
#define VOCAB 256
#define NBLK 148
#define NTHR 512
#define UPB 14             // hidden units per block (148*14 >= 2048)
#define NROWS_MAX (3 * UPB)   // 42

// SMEM: high-k half of weights [42][1024] fp16 | hs[2048] fp16
#define WS2_HALFS 1024
#define WS2_BYTES (NROWS_MAX * WS2_HALFS * 2)   // 86016
#define HS_OFF WS2_BYTES
#define SMEM_TOTAL (HS_OFF + H_DIM * 2)         // 90112

// ---------------- scratch (static device memory, no allocs) ----------------
__device__ float g_tbl[VOCAB * G3];   // W_ih@emb[v] + b_ih (+b_hh folded for r,z)
__device__ float g_h[2][H_DIM];       // hidden state fp32, double-buffered
__device__ unsigned g_cnt;            // monotonic phased barrier counter

// ---------------- sync primitives --------------------------------------------
__device__ __forceinline__ unsigned ld_acq(const unsigned* p) {
    unsigned v;
    asm volatile("ld.acquire.gpu.global.b32 %0, [%1];" : "=r"(v) : "l"(p) : "memory");
    return v;
}
__device__ __forceinline__ void red_rel_add1(unsigned* p) {
    asm volatile("red.release.gpu.global.add.u32 [%0], %1;" :: "l"(p), "r"(1u) : "memory");
}

// ---------------- packed f32x2 helpers ---------------------------------------
__device__ __forceinline__ unsigned long long pk(float x, float y) {
    unsigned long long r;
    asm("mov.b64 %0, {%1, %2};" : "=l"(r) : "f"(x), "f"(y));
    return r;
}
__device__ __forceinline__ float2 unpk(unsigned long long v) {
    float2 r;
    asm("mov.b64 {%0, %1}, %2;" : "=f"(r.x), "=f"(r.y) : "l"(v));
    return r;
}
__device__ __forceinline__ void fma2(unsigned long long& d,
                                     unsigned long long a, unsigned long long b) {
    asm("fma.rn.f32x2 %0, %1, %2, %0;" : "+l"(d) : "l"(a), "l"(b));
}
// 8 fp16 weights (uint4) dotted against 8 fp16 h values (4 packed f32x2)
__device__ __forceinline__ void dotq(uint4 w,
    unsigned long long hp0, unsigned long long hp1,
    unsigned long long hp2, unsigned long long hp3,
    unsigned long long& aA, unsigned long long& aB) {
    float2 f0 = __half22float2(*(__half2*)&w.x);
    float2 f1 = __half22float2(*(__half2*)&w.y);
    float2 f2 = __half22float2(*(__half2*)&w.z);
    float2 f3 = __half22float2(*(__half2*)&w.w);
    fma2(aA, pk(f0.x, f0.y), hp0);
    fma2(aB, pk(f1.x, f1.y), hp1);
    fma2(aA, pk(f2.x, f2.y), hp2);
    fma2(aB, pk(f3.x, f3.y), hp3);
}
__device__ __forceinline__ uint4 pack4(float4 a, float4 b) {
    uint4 r; __half2 h;
    h = __floats2half2_rn(a.x, a.y); r.x = *(unsigned*)&h;
    h = __floats2half2_rn(a.z, a.w); r.y = *(unsigned*)&h;
    h = __floats2half2_rn(b.x, b.y); r.z = *(unsigned*)&h;
    h = __floats2half2_rn(b.z, b.w); r.w = *(unsigned*)&h;
    return r;
}

// ---------------- kernel 1: ih table GEMM + state/counter init --------------
__global__ __launch_bounds__(256) void tbl_kernel(
    const float* __restrict__ emb,
    const float* __restrict__ w_ih,
    const float* __restrict__ b_ih,
    const float* __restrict__ b_hh)
{
    __shared__ float Es[32][33];
    __shared__ float Ws[64][33];
    const int tid = threadIdx.x;
    const int j0 = blockIdx.x * 64;
    const int v0 = blockIdx.y * 32;

    if (blockIdx.x == 0 && blockIdx.y == 0) {
        for (int i = tid; i < 2 * H_DIM; i += 256) ((float*)g_h)[i] = 0.f;
        if (tid == 0) g_cnt = 0u;
    }

    float acc[8] = {0.f, 0.f, 0.f, 0.f, 0.f, 0.f, 0.f, 0.f};
    const int jj = tid & 63;
    const int vb = (tid >> 6) * 8;

    for (int k0 = 0; k0 < E_DIM; k0 += 32) {
        __syncthreads();
        #pragma unroll
        for (int p = 0; p < 4; p++) {
            int idx = tid + p * 256;
            Es[idx >> 5][idx & 31] = emb[(size_t)(v0 + (idx >> 5)) * E_DIM + k0 + (idx & 31)];
        }
        #pragma unroll
        for (int p = 0; p < 8; p++) {
            int idx = tid + p * 256;
            Ws[idx >> 5][idx & 31] = w_ih[(size_t)(j0 + (idx >> 5)) * E_DIM + k0 + (idx & 31)];
        }
        __syncthreads();
        #pragma unroll
        for (int kk = 0; kk < 32; kk++) {
            float w = Ws[jj][kk];
            #pragma unroll
            for (int r = 0; r < 8; r++) acc[r] += w * Es[vb + r][kk];
        }
    }
    const int j = j0 + jj;
    float bias = b_ih[j] + ((j < 2 * H_DIM) ? b_hh[j] : 0.f);
    #pragma unroll
    for (int r = 0; r < 8; r++)
        g_tbl[(size_t)(v0 + vb + r) * G3 + j] = acc[r] + bias;
}

// ---------------- kernel 2: persistent GRU (R6 skeleton, fp16 h staging) ----
// Warp w of block b owns hidden unit u = b*14 + w. Weights k<1024 in 48 regs
// (packed half2), k>=1024 in SMEM fp16. h staged into SMEM as fp16; the
// recurrent h for each unit stays fp32 in lane0's register. Grid sync =
// monotonic counter, one release-RED per block per step.
__global__ void __launch_bounds__(NTHR, 1) gru_kernel(
    const int*   __restrict__ x,
    const int*   __restrict__ lenp,
    const float* __restrict__ w_hh,    // [G3, H] fp32
    const float* __restrict__ b_hh,    // [G3]
    const float* __restrict__ dec_emb, // [128, E]
    float*       __restrict__ out,     // [E + H]
    int n_x)
{
    extern __shared__ __align__(16) unsigned char smem_raw[];
    __half* ws = (__half*)smem_raw;              // [42][1024] high-k weights
    __half* hs = (__half*)(smem_raw + HS_OFF);   // [2048] staged h (fp16)

    const int tid  = threadIdx.x;
    const int b    = blockIdx.x;
    const int lane = tid & 31;
    const int wid  = tid >> 5;

    const int u0 = b * UPB;
    int nu = H_DIM - u0;
    if (nu > UPB) nu = UPB;
    if (nu < 0) nu = 0;
    const bool writer = (wid < nu);
    const int u = u0 + wid;

    // ---- prologue: low-k halves -> registers, high-k halves -> SMEM ----
    uint4 wreg[12];   // [row*4 + c], c = 0..3 covers k in [0,1024)
    if (writer) {
        #pragma unroll
        for (int r = 0; r < 3; r++) {
            const float4* src = (const float4*)(w_hh + (size_t)(r * H_DIM + u) * H_DIM);
            #pragma unroll
            for (int c = 0; c < 4; c++) {
                float4 a = __ldcs(src + c * 64 + lane * 2);
                float4 q = __ldcs(src + c * 64 + lane * 2 + 1);
                wreg[r * 4 + c] = pack4(a, q);
            }
            uint4* dst = (uint4*)(ws + (size_t)(3 * wid + r) * WS2_HALFS);
            #pragma unroll
            for (int c = 0; c < 4; c++) {
                float4 a = __ldcs(src + 256 + c * 64 + lane * 2);
                float4 q = __ldcs(src + 256 + c * 64 + lane * 2 + 1);
                dst[c * 32 + lane] = pack4(a, q);
            }
        }
    }

    float bhn = 0.f;
    if (writer && lane == 0) bhn = __ldg(&b_hh[2 * H_DIM + u]);
    float hold = 0.f;   // fp32 recurrent h for this unit (lane0)

    int steps = lenp[0] + 1;
    if (steps > n_x) steps = n_x;

    const uint4* wrow0 = (const uint4*)(ws + (size_t)(3 * wid)     * WS2_HALFS);
    const uint4* wrow1 = (const uint4*)(ws + (size_t)(3 * wid + 1) * WS2_HALFS);
    const uint4* wrow2 = (const uint4*)(ws + (size_t)(3 * wid + 2) * WS2_HALFS);
    const uint4* hs16 = (const uint4*)hs;

    unsigned target = 0;

    for (int t = 0; t < steps; ++t) {
        // hoisted step-t constants: L2 latency hides under the barrier poll
        float ih_r = 0.f, ih_z = 0.f, ih_n = 0.f;
        if (writer && lane == 0) {
            const int xt = __ldg(&x[t]);
            const float* __restrict__ tbl = g_tbl + (size_t)xt * G3;
            ih_r = __ldg(&tbl[u]);
            ih_z = __ldg(&tbl[u + H_DIM]);
            ih_n = __ldg(&tbl[u + 2 * H_DIM]);
        }

        // ---- wait: all blocks finished step t-1 ----
        if (tid == 0) {
            while (ld_acq(&g_cnt) < target) { }
        }
        __syncthreads();

        const int prev = t & 1;

        // ---- stage h(t-1) into SMEM as fp16 (512 threads x 4 floats) ----
        {
            float4 v = __ldcg(((const float4*)g_h[prev]) + tid);
            uint2 o; __half2 h;
            h = __floats2half2_rn(v.x, v.y); o.x = *(unsigned*)&h;
            h = __floats2half2_rn(v.z, v.w); o.y = *(unsigned*)&h;
            ((uint2*)hs)[tid] = o;
        }
        __syncthreads();

        if (writer) {
            unsigned long long a00 = 0ull, a01 = 0ull;
            unsigned long long a10 = 0ull, a11 = 0ull;
            unsigned long long a20 = 0ull, a21 = 0ull;
            #pragma unroll
            for (int c = 0; c < 8; c++) {
                uint4 hw = hs16[c * 32 + lane];   // 8 fp16 h values
                float2 g0 = __half22float2(*(__half2*)&hw.x);
                float2 g1 = __half22float2(*(__half2*)&hw.y);
                float2 g2 = __half22float2(*(__half2*)&hw.z);
                float2 g3 = __half22float2(*(__half2*)&hw.w);
                unsigned long long hp0 = pk(g0.x, g0.y);
                unsigned long long hp1 = pk(g1.x, g1.y);
                unsigned long long hp2 = pk(g2.x, g2.y);
                unsigned long long hp3 = pk(g3.x, g3.y);
                uint4 w0 = (c < 4) ? wreg[0 * 4 + c] : wrow0[(c - 4) * 32 + lane];
                uint4 w1 = (c < 4) ? wreg[1 * 4 + c] : wrow1[(c - 4) * 32 + lane];
                uint4 w2 = (c < 4) ? wreg[2 * 4 + c] : wrow2[(c - 4) * 32 + lane];
                dotq(w0, hp0, hp1, hp2, hp3, a00, a01);
                dotq(w1, hp0, hp1, hp2, hp3, a10, a11);
                dotq(w2, hp0, hp1, hp2, hp3, a20, a21);
            }
            float2 s;
            float a0, a1, a2;
            s = unpk(a00); a0 = s.x + s.y;  s = unpk(a01); a0 += s.x + s.y;
            s = unpk(a10); a1 = s.x + s.y;  s = unpk(a11); a1 += s.x + s.y;
            s = unpk(a20); a2 = s.x + s.y;  s = unpk(a21); a2 += s.x + s.y;
            #pragma unroll
            for (int o = 16; o; o >>= 1) {
                a0 += __shfl_xor_sync(0xffffffffu, a0, o);
                a1 += __shfl_xor_sync(0xffffffffu, a1, o);
                a2 += __shfl_xor_sync(0xffffffffu, a2, o);
            }
            if (lane == 0) {
                float r = 1.f / (1.f + __expf(-(a0 + ih_r)));  // biases folded in tbl
                float z = 1.f / (1.f + __expf(-(a1 + ih_z)));
                float v = ih_n + r * (a2 + bhn);
                float e = __expf(2.f * v);
                float n = 1.f - __fdividef(2.f, e + 1.f);       // tanh(v)
                float hnew = (1.f - z) * n + z * hold;
                hold = hnew;
                __stcg(&g_h[prev ^ 1][u], hnew);
            }
        }
        __syncthreads();

        // ---- arrive: one release-RED per block ----
        if (tid == 0) red_rel_add1(&g_cnt);
        target += NBLK;
    }

    if (b == 0) {
        if (tid == 0) {
            while (ld_acq(&g_cnt) < target) { }
        }
        __syncthreads();
        const int last = steps & 1;
        for (int i = tid; i < E_DIM; i += NTHR) out[i] = dec_emb[2 * E_DIM + i];
        for (int i = tid; i < H_DIM; i += NTHR) out[E_DIM + i] = __ldcg(&g_h[last][i]);
    }
}

// ---------------- launch ----------------------------------------------------
extern "C" void kernel_launch(void* const* d_in, const int* in_sizes, int n_in,
                              void* d_out, int out_size) {
    const int*   x       = (const int*)d_in[0];
    const int*   lenp    = (const int*)d_in[1];
    const float* enc_emb = (const float*)d_in[2];
    const float* w_ih    = (const float*)d_in[3];
    const float* w_hh    = (const float*)d_in[4];
    const float* b_ih    = (const float*)d_in[5];
    const float* b_hh    = (const float*)d_in[6];
    const float* dec_emb = (const float*)d_in[7];
    float* out = (float*)d_out;
    const int n_x = in_sizes[0];

    static int attr_set = 0;
    if (!attr_set) {
        cudaFuncSetAttribute(gru_kernel, cudaFuncAttributeMaxDynamicSharedMemorySize,
                             SMEM_TOTAL);
        attr_set = 1;
    }

    dim3 tgrid(G3 / 64, VOCAB / 32);   // 96 x 8
    tbl_kernel<<<tgrid, 256>>>(enc_emb, w_ih, b_ih, b_hh);
    gru_kernel<<<NBLK, NTHR, SMEM_TOTAL>>>(x, lenp, w_hh, b_hh, dec_emb, out, n_x);
}